// round 12
// baseline (speedup 1.0000x reference)
#include <cuda_runtime.h>
#include <cstdint>

// GlobalAttentionModule_7438883356930
//
// Identity: softmax row-sums are 1 and v is constant along the softmaxed axis,
// so out = relu(GroupNorm_32(Wv @ feat + bv)). (Verified: rel_err ~1e-7.)
//
// R11: keep R10 skeleton (grid=128 one wave, cluster-2 per (b,g), 512 thr,
// k split 8 ways). Chain surgery:
//  - feat LDG.128s front-batched into registers before the weight barrier
//  - both cluster.syncs + DSMEM pull replaced by push-style mbarrier
//    handshake (st.shared::cluster + arrive.release.cluster, count=2)
//  - mean/rstd computed redundantly per-thread from the two slots (det.)

#define C_DIM    128
#define N_DIM    512
#define B_DIM    2
#define GROUPS   32
#define CPG      4
#define HALVES   2                     // cluster size
#define HALF_N   (N_DIM / HALVES)      // 256
#define NF4      (HALF_N / 4)          // 64 float4 n-positions
#define KSPLIT   8
#define KPART    (C_DIM / KSPLIT)      // 16
#define THREADS  (KSPLIT * NF4)        // 512
#define EPS      1e-5f

__device__ __forceinline__ uint32_t smem_u32(const void* p) {
    return (uint32_t)__cvta_generic_to_shared(p);
}

__global__ __launch_bounds__(THREADS) __cluster_dims__(HALVES, 1, 1)
void fused_onewave(const float* __restrict__ feat,   // [B, C, N]
                   const float* __restrict__ Wv,     // [C, C]
                   const float* __restrict__ bv,     // [C]
                   const float* __restrict__ gamma,  // [C]
                   const float* __restrict__ beta,   // [C]
                   float* __restrict__ out)          // [B, C, N]
{
    const int bg   = blockIdx.x / HALVES;    // (batch, group)
    const int half = blockIdx.x % HALVES;    // cluster rank
    const int peer = half ^ 1;
    const int b    = bg / GROUPS;
    const int g    = bg % GROUPS;
    const int t    = threadIdx.x;

    __shared__ float4 wT[C_DIM];                    // 2 KB: wT[k] = {w_c0..w_c3}[k]
    __shared__ float4 scomb[KSPLIT][CPG][NF4];      // 32 KB k-slice partials
    __shared__ float  red_s[8], red_ss[8];
    __shared__ float2 slots[HALVES];                // per-source-rank partials
    __shared__ __align__(8) unsigned long long mbar;

    const int q = t >> 6;          // k-slice 0..7
    const int j = t & 63;          // float4 n index 0..63

    // ---- init mbarrier (2 arrivals: one per block's t0) ----
    if (t == 0) {
        asm volatile("mbarrier.init.shared.b64 [%0], 2;"
                     :: "r"(smem_u32(&mbar)) : "memory");
    }
    __syncthreads();
    // split cluster barrier: arrive now, wait much later (init visibility)
    asm volatile("barrier.cluster.arrive.aligned;" ::: "memory");

    // ---- front-batch ALL feat loads into registers (MLP ~17) ----
    float4 x[KPART];
    {
        const float* fb = feat + (size_t)b * C_DIM * N_DIM
                        + (size_t)(q * KPART) * N_DIM + half * HALF_N + 4 * j;
        #pragma unroll
        for (int kk = 0; kk < KPART; kk++)
            x[kk] = *reinterpret_cast<const float4*>(fb + (size_t)kk * N_DIM);
    }

    // ---- stage weights transposed (overlaps with feat loads in flight) ----
    {
        const int k  = t & 127;
        const int cc = t >> 7;     // 0..3
        reinterpret_cast<float*>(&wT[k])[cc] = Wv[(size_t)(g * CPG + cc) * C_DIM + k];
    }
    __syncthreads();

    // ---- GEMM: 4ch x 4n tile over this thread's 16 k values ----
    float4 a0 = make_float4(0.f, 0.f, 0.f, 0.f);
    float4 a1 = a0, a2 = a0, a3 = a0;
    #pragma unroll
    for (int kk = 0; kk < KPART; kk++) {
        const float4 wv = wT[q * KPART + kk];
        const float4 xv = x[kk];
        a0.x = fmaf(wv.x, xv.x, a0.x); a0.y = fmaf(wv.x, xv.y, a0.y);
        a0.z = fmaf(wv.x, xv.z, a0.z); a0.w = fmaf(wv.x, xv.w, a0.w);
        a1.x = fmaf(wv.y, xv.x, a1.x); a1.y = fmaf(wv.y, xv.y, a1.y);
        a1.z = fmaf(wv.y, xv.z, a1.z); a1.w = fmaf(wv.y, xv.w, a1.w);
        a2.x = fmaf(wv.z, xv.x, a2.x); a2.y = fmaf(wv.z, xv.y, a2.y);
        a2.z = fmaf(wv.z, xv.z, a2.z); a2.w = fmaf(wv.z, xv.w, a2.w);
        a3.x = fmaf(wv.w, xv.x, a3.x); a3.y = fmaf(wv.w, xv.y, a3.y);
        a3.z = fmaf(wv.w, xv.z, a3.z); a3.w = fmaf(wv.w, xv.w, a3.w);
    }

    // ---- publish k-slice partials ----
    scomb[q][0][j] = a0;
    scomb[q][1][j] = a1;
    scomb[q][2][j] = a2;
    scomb[q][3][j] = a3;
    __syncthreads();

    // ---- fold by 256 epilogue threads; block-level stats ----
    const int ecc = t >> 6;        // 0..3 for t<256
    const int ej  = t & 63;
    float4 v = make_float4(0.f, 0.f, 0.f, 0.f);
    float ga_raw = 0.f, be = 0.f;

    if (t < 256) {
        #pragma unroll
        for (int r = 0; r < KSPLIT; r++) {
            const float4 p = scomb[r][ecc][ej];
            v.x += p.x; v.y += p.y; v.z += p.z; v.w += p.w;
        }
        const int c  = g * CPG + ecc;
        const float bb = bv[c];
        v.x += bb; v.y += bb; v.z += bb; v.w += bb;

        ga_raw = gamma[c];         // prefetch; hides under handshake
        be     = beta[c];

        float s  = v.x + v.y + v.z + v.w;
        float ss = v.x * v.x + v.y * v.y + v.z * v.z + v.w * v.w;
        #pragma unroll
        for (int o = 16; o > 0; o >>= 1) {
            s  += __shfl_xor_sync(0xffffffffu, s,  o);
            ss += __shfl_xor_sync(0xffffffffu, ss, o);
        }
        const int warp = t >> 5, lane = t & 31;     // warps 0..7
        if (lane == 0) { red_s[warp] = s; red_ss[warp] = ss; }
    }
    __syncthreads();

    // ---- peer's mbarrier is init'd by now (arrive was at the top) ----
    asm volatile("barrier.cluster.wait.aligned;" ::: "memory");

    if (t == 0) {
        float ts = 0.f, tss = 0.f;
        #pragma unroll
        for (int i = 0; i < 8; i++) { ts += red_s[i]; tss += red_ss[i]; }

        // push my partial into BOTH blocks' slots[half], then arrive on both
        const uint32_t lslot = smem_u32(&slots[half]);
        uint32_t rslot;
        asm("mapa.shared::cluster.u32 %0, %1, %2;"
            : "=r"(rslot) : "r"(lslot), "r"(peer));
        asm volatile("st.shared::cluster.v2.f32 [%0], {%1, %2};"
                     :: "r"(rslot), "f"(ts), "f"(tss) : "memory");
        slots[half] = make_float2(ts, tss);

        const uint32_t lmb = smem_u32(&mbar);
        uint32_t rmb;
        asm("mapa.shared::cluster.u32 %0, %1, %2;"
            : "=r"(rmb) : "r"(lmb), "r"(peer));
        asm volatile("mbarrier.arrive.release.cluster.shared::cluster.b64 _, [%0];"
                     :: "r"(rmb) : "memory");
        asm volatile("mbarrier.arrive.release.cluster.shared::cta.b64 _, [%0];"
                     :: "r"(lmb) : "memory");
    }

    // ---- all threads wait for both arrivals (phase 0) ----
    {
        const uint32_t mb = smem_u32(&mbar);
        asm volatile(
            "{\n\t"
            ".reg .pred P;\n\t"
            "WAIT_%=:\n\t"
            "mbarrier.try_wait.parity.acquire.cluster.shared::cta.b64 P, [%0], 0, 0x989680;\n\t"
            "@P bra DONE_%=;\n\t"
            "bra WAIT_%=;\n\t"
            "DONE_%=:\n\t"
            "}"
            :: "r"(mb) : "memory");
    }

    // ---- redundant per-thread stats (fixed order -> deterministic) ----
    if (t < 256) {
        const float2 p0 = slots[0];
        const float2 p1 = slots[1];
        const float inv = 1.0f / (float)(CPG * N_DIM);
        const float m   = (p0.x + p1.x) * inv;
        const float var = (p0.y + p1.y) * inv - m * m;
        const float ga  = ga_raw * rsqrtf(var + EPS);

        const int c  = g * CPG + ecc;
        const int n0 = half * HALF_N + 4 * ej;

        float4 o4;
        o4.x = fmaxf(fmaf(v.x - m, ga, be), 0.f);
        o4.y = fmaxf(fmaf(v.y - m, ga, be), 0.f);
        o4.z = fmaxf(fmaf(v.z - m, ga, be), 0.f);
        o4.w = fmaxf(fmaf(v.w - m, ga, be), 0.f);
        *reinterpret_cast<float4*>(out + ((size_t)b * C_DIM + c) * N_DIM + n0) = o4;
    }
    // Exit safe: we only pass the wait after the peer's release-arrive, which
    // orders its remote store into our smem; nobody touches peer smem after.
}

extern "C" void kernel_launch(void* const* d_in, const int* in_sizes, int n_in,
                              void* d_out, int out_size)
{
    // 0 feat, 1 Wk, 2 bk, 3 Wq, 4 bq, 5 Wv, 6 bv, 7 gn_v_g, 8 gn_v_b, ...
    const float* feat = (const float*)d_in[0];
    const float* Wv   = (const float*)d_in[5];
    const float* bv   = (const float*)d_in[6];
    const float* gn_g = (const float*)d_in[7];
    const float* gn_b = (const float*)d_in[8];
    float* out = (float*)d_out;

    fused_onewave<<<B_DIM * GROUPS * HALVES, THREADS>>>(feat, Wv, bv, gn_g, gn_b, out);
}

// round 13
// speedup vs baseline: 1.1111x; 1.1111x over previous
#include <cuda_runtime.h>
#include <cstdint>

// GlobalAttentionModule_7438883356930
//
// Identity: softmax row-sums are 1 and v is constant along the softmaxed axis,
// so out = relu(GroupNorm_32(Wv @ feat + bv)). (Verified: rel_err ~1e-7.)
//
// R12 = R10 skeleton (grid=128 one wave, cluster-2 per (b,g), 512 thr,
// k split 8 ways, cluster.sync + DSMEM-pull stats — the 8.70us config),
// plus: (a) feat LDG.128 front-batched as ulonglong2 (f32x2 pairs),
// (b) packed fma.rn.f32x2 mainloop -> FMA-pipe issue cycles halved,
// (c) add.rn.f32x2 fold.

#define C_DIM    128
#define N_DIM    512
#define B_DIM    2
#define GROUPS   32
#define CPG      4
#define HALVES   2                     // cluster size
#define HALF_N   (N_DIM / HALVES)      // 256
#define NF4      (HALF_N / 4)          // 64 float4 n-positions
#define KSPLIT   8
#define KPART    (C_DIM / KSPLIT)      // 16
#define THREADS  (KSPLIT * NF4)        // 512
#define EPS      1e-5f

__device__ __forceinline__ uint32_t smem_u32(const void* p) {
    return (uint32_t)__cvta_generic_to_shared(p);
}

#define FMA2(acc, a, b) \
    asm("fma.rn.f32x2 %0, %1, %2, %0;" : "+l"(acc) : "l"(a), "l"(b))
#define ADD2(acc, a) \
    asm("add.rn.f32x2 %0, %0, %1;" : "+l"(acc) : "l"(a))
#define DUP2(d, s) \
    asm("mov.b64 %0, {%1, %1};" : "=l"(d) : "f"(s))
#define UNPK2(lo, hi, s) \
    asm("mov.b64 {%0, %1}, %2;" : "=f"(lo), "=f"(hi) : "l"(s))

__global__ __launch_bounds__(THREADS) __cluster_dims__(HALVES, 1, 1)
void fused_onewave(const float* __restrict__ feat,   // [B, C, N]
                   const float* __restrict__ Wv,     // [C, C]
                   const float* __restrict__ bv,     // [C]
                   const float* __restrict__ gamma,  // [C]
                   const float* __restrict__ beta,   // [C]
                   float* __restrict__ out)          // [B, C, N]
{
    const int bg   = blockIdx.x / HALVES;    // (batch, group)
    const int half = blockIdx.x % HALVES;    // cluster rank
    const int b    = bg / GROUPS;
    const int g    = bg % GROUPS;
    const int t    = threadIdx.x;

    __shared__ float4 wT[C_DIM];                    // 2 KB: wT[k] = {w_c0..w_c3}[k]
    __shared__ float4 scomb[KSPLIT][CPG][NF4];      // 32 KB k-slice partials
    __shared__ float  red_s[8], red_ss[8];
    __shared__ float2 part;                         // DSMEM-visible (sum, sumsq)
    __shared__ float  s_mean, s_rstd;

    const int q = t >> 6;          // k-slice 0..7
    const int j = t & 63;          // float4 n index 0..63

    // ---- front-batch ALL feat loads (LDG.128 -> two packed f32x2 each) ----
    ulonglong2 x[KPART];
    {
        const float* fb = feat + (size_t)b * C_DIM * N_DIM
                        + (size_t)(q * KPART) * N_DIM + half * HALF_N + 4 * j;
        #pragma unroll
        for (int kk = 0; kk < KPART; kk++)
            x[kk] = *reinterpret_cast<const ulonglong2*>(fb + (size_t)kk * N_DIM);
    }

    // ---- stage weights transposed (overlaps with feat loads in flight) ----
    {
        const int k  = t & 127;
        const int cc = t >> 7;     // 0..3
        reinterpret_cast<float*>(&wT[k])[cc] = Wv[(size_t)(g * CPG + cc) * C_DIM + k];
    }
    __syncthreads();

    // ---- GEMM: 4ch x 4n tile, packed f32x2 (8 FFMA2 + 4 dup-movs per k) ----
    unsigned long long A0l = 0, A0h = 0, A1l = 0, A1h = 0;
    unsigned long long A2l = 0, A2h = 0, A3l = 0, A3h = 0;
    #pragma unroll
    for (int kk = 0; kk < KPART; kk++) {
        const float4 wv = wT[q * KPART + kk];
        unsigned long long w0, w1, w2, w3;
        DUP2(w0, wv.x); DUP2(w1, wv.y); DUP2(w2, wv.z); DUP2(w3, wv.w);
        const unsigned long long xl = x[kk].x, xh = x[kk].y;
        FMA2(A0l, w0, xl); FMA2(A0h, w0, xh);
        FMA2(A1l, w1, xl); FMA2(A1h, w1, xh);
        FMA2(A2l, w2, xl); FMA2(A2h, w2, xh);
        FMA2(A3l, w3, xl); FMA2(A3h, w3, xh);
    }

    // ---- publish k-slice partials (still 16B stores) ----
    *reinterpret_cast<ulonglong2*>(&scomb[q][0][j]) = make_ulonglong2(A0l, A0h);
    *reinterpret_cast<ulonglong2*>(&scomb[q][1][j]) = make_ulonglong2(A1l, A1h);
    *reinterpret_cast<ulonglong2*>(&scomb[q][2][j]) = make_ulonglong2(A2l, A2h);
    *reinterpret_cast<ulonglong2*>(&scomb[q][3][j]) = make_ulonglong2(A3l, A3h);
    __syncthreads();

    // ---- fold by 256 epilogue threads (add.rn.f32x2); block-level stats ----
    const int ecc = t >> 6;        // 0..3 for t<256
    const int ej  = t & 63;
    float v0 = 0.f, v1 = 0.f, v2 = 0.f, v3 = 0.f;
    float ga_raw = 0.f, be = 0.f;

    if (t < 256) {
        unsigned long long vl = 0, vh = 0;
        #pragma unroll
        for (int r = 0; r < KSPLIT; r++) {
            const ulonglong2 p = *reinterpret_cast<const ulonglong2*>(&scomb[r][ecc][ej]);
            ADD2(vl, p.x);
            ADD2(vh, p.y);
        }
        const int c  = g * CPG + ecc;
        unsigned long long bb2;
        DUP2(bb2, bv[c]);
        ADD2(vl, bb2);
        ADD2(vh, bb2);
        UNPK2(v0, v1, vl);
        UNPK2(v2, v3, vh);

        ga_raw = gamma[c];         // prefetch; hides under stats + barrier
        be     = beta[c];

        float s  = v0 + v1 + v2 + v3;
        float ss = v0 * v0 + v1 * v1 + v2 * v2 + v3 * v3;
        #pragma unroll
        for (int o = 16; o > 0; o >>= 1) {
            s  += __shfl_xor_sync(0xffffffffu, s,  o);
            ss += __shfl_xor_sync(0xffffffffu, ss, o);
        }
        const int warp = t >> 5, lane = t & 31;     // warps 0..7
        if (lane == 0) { red_s[warp] = s; red_ss[warp] = ss; }
    }
    __syncthreads();
    if (t == 0) {
        float ts = 0.f, tss = 0.f;
        #pragma unroll
        for (int i = 0; i < 8; i++) { ts += red_s[i]; tss += red_ss[i]; }
        part = make_float2(ts, tss);
    }

    // ---- cluster barrier 1: both halves' `part` published ----
    asm volatile("barrier.cluster.arrive.aligned;" ::: "memory");
    asm volatile("barrier.cluster.wait.aligned;"   ::: "memory");

    // ---- fold 2 peer partials via DSMEM (deterministic) ----
    if (t == 0) {
        float fs = 0.f, fss = 0.f;
        const uint32_t local = smem_u32(&part);
        #pragma unroll
        for (int r = 0; r < HALVES; r++) {
            uint32_t remote;
            asm("mapa.shared::cluster.u32 %0, %1, %2;"
                : "=r"(remote) : "r"(local), "r"(r));
            float px, py;
            asm volatile("ld.shared::cluster.v2.f32 {%0, %1}, [%2];"
                         : "=f"(px), "=f"(py) : "r"(remote));
            fs += px; fss += py;
        }
        const float inv = 1.0f / (float)(CPG * N_DIM);
        const float m   = fs * inv;
        const float var = fss * inv - m * m;
        s_mean = m;
        s_rstd = rsqrtf(var + EPS);
    }

    // ---- cluster barrier 2: DSMEM reads done (safe to exit after) ----
    asm volatile("barrier.cluster.arrive.aligned;" ::: "memory");
    asm volatile("barrier.cluster.wait.aligned;"   ::: "memory");
    __syncthreads();

    // ---- normalize + affine + relu + store (256 epilogue threads) ----
    if (t < 256) {
        const float m  = s_mean;
        const float ga = ga_raw * s_rstd;
        const int  c   = g * CPG + ecc;
        const int  n0  = half * HALF_N + 4 * ej;

        float4 o4;
        o4.x = fmaxf(fmaf(v0 - m, ga, be), 0.f);
        o4.y = fmaxf(fmaf(v1 - m, ga, be), 0.f);
        o4.z = fmaxf(fmaf(v2 - m, ga, be), 0.f);
        o4.w = fmaxf(fmaf(v3 - m, ga, be), 0.f);
        *reinterpret_cast<float4*>(out + ((size_t)b * C_DIM + c) * N_DIM + n0) = o4;
    }
}

extern "C" void kernel_launch(void* const* d_in, const int* in_sizes, int n_in,
                              void* d_out, int out_size)
{
    // 0 feat, 1 Wk, 2 bk, 3 Wq, 4 bq, 5 Wv, 6 bv, 7 gn_v_g, 8 gn_v_b, ...
    const float* feat = (const float*)d_in[0];
    const float* Wv   = (const float*)d_in[5];
    const float* bv   = (const float*)d_in[6];
    const float* gn_g = (const float*)d_in[7];
    const float* gn_b = (const float*)d_in[8];
    float* out = (float*)d_out;

    fused_onewave<<<B_DIM * GROUPS * HALVES, THREADS>>>(feat, Wv, bv, gn_g, gn_b, out);
}

// round 14
// speedup vs baseline: 1.1654x; 1.0489x over previous
#include <cuda_runtime.h>
#include <cstdint>

// GlobalAttentionModule_7438883356930
//
// Identity: softmax row-sums are 1 and v is constant along the softmaxed axis,
// so out = relu(GroupNorm_32(Wv @ feat + bv)). (Verified: rel_err ~1e-7.)
//
// R13 = R10 config (grid=128 one wave, cluster-2 per (b,g), 512 thr, k split
// 8 ways, plain FFMA mainloop — the 8.70us best) with the sync chain cut:
//  - feat LDG.128s front-batched before the weight-stage barrier
//  - stats exchanged by PUSH (st.shared::cluster) + ONE cluster.sync
//    (arrive has release semantics), replacing 2 cluster syncs + DSMEM pull
//    + final __syncthreads. mean/rstd computed redundantly, fixed order.

#define C_DIM    128
#define N_DIM    512
#define B_DIM    2
#define GROUPS   32
#define CPG      4
#define HALVES   2                     // cluster size
#define HALF_N   (N_DIM / HALVES)      // 256
#define NF4      (HALF_N / 4)          // 64 float4 n-positions
#define KSPLIT   8
#define KPART    (C_DIM / KSPLIT)      // 16
#define THREADS  (KSPLIT * NF4)        // 512
#define EPS      1e-5f

__device__ __forceinline__ uint32_t smem_u32(const void* p) {
    return (uint32_t)__cvta_generic_to_shared(p);
}

__global__ __launch_bounds__(THREADS) __cluster_dims__(HALVES, 1, 1)
void fused_onewave(const float* __restrict__ feat,   // [B, C, N]
                   const float* __restrict__ Wv,     // [C, C]
                   const float* __restrict__ bv,     // [C]
                   const float* __restrict__ gamma,  // [C]
                   const float* __restrict__ beta,   // [C]
                   float* __restrict__ out)          // [B, C, N]
{
    const int bg   = blockIdx.x / HALVES;    // (batch, group)
    const int half = blockIdx.x % HALVES;    // cluster rank
    const int peer = half ^ 1;
    const int b    = bg / GROUPS;
    const int g    = bg % GROUPS;
    const int t    = threadIdx.x;

    __shared__ float4 wT[C_DIM];                    // 2 KB: wT[k] = {w_c0..w_c3}[k]
    __shared__ float4 scomb[KSPLIT][CPG][NF4];      // 32 KB k-slice partials
    __shared__ float  red_s[8], red_ss[8];
    __shared__ float2 slots[HALVES];                // partials indexed by source rank

    const int q = t >> 6;          // k-slice 0..7
    const int j = t & 63;          // float4 n index 0..63

    // ---- front-batch ALL feat loads into registers (MLP ~16) ----
    float4 x[KPART];
    {
        const float* fb = feat + (size_t)b * C_DIM * N_DIM
                        + (size_t)(q * KPART) * N_DIM + half * HALF_N + 4 * j;
        #pragma unroll
        for (int kk = 0; kk < KPART; kk++)
            x[kk] = *reinterpret_cast<const float4*>(fb + (size_t)kk * N_DIM);
    }

    // ---- stage weights transposed (overlaps with feat loads in flight) ----
    {
        const int k  = t & 127;
        const int cc = t >> 7;     // 0..3
        reinterpret_cast<float*>(&wT[k])[cc] = Wv[(size_t)(g * CPG + cc) * C_DIM + k];
    }
    __syncthreads();

    // ---- GEMM: 4ch x 4n tile over this thread's 16 k values (plain FFMA) ----
    float4 a0 = make_float4(0.f, 0.f, 0.f, 0.f);
    float4 a1 = a0, a2 = a0, a3 = a0;
    #pragma unroll
    for (int kk = 0; kk < KPART; kk++) {
        const float4 wv = wT[q * KPART + kk];
        const float4 xv = x[kk];
        a0.x = fmaf(wv.x, xv.x, a0.x); a0.y = fmaf(wv.x, xv.y, a0.y);
        a0.z = fmaf(wv.x, xv.z, a0.z); a0.w = fmaf(wv.x, xv.w, a0.w);
        a1.x = fmaf(wv.y, xv.x, a1.x); a1.y = fmaf(wv.y, xv.y, a1.y);
        a1.z = fmaf(wv.y, xv.z, a1.z); a1.w = fmaf(wv.y, xv.w, a1.w);
        a2.x = fmaf(wv.z, xv.x, a2.x); a2.y = fmaf(wv.z, xv.y, a2.y);
        a2.z = fmaf(wv.z, xv.z, a2.z); a2.w = fmaf(wv.z, xv.w, a2.w);
        a3.x = fmaf(wv.w, xv.x, a3.x); a3.y = fmaf(wv.w, xv.y, a3.y);
        a3.z = fmaf(wv.w, xv.z, a3.z); a3.w = fmaf(wv.w, xv.w, a3.w);
    }

    // ---- publish k-slice partials ----
    scomb[q][0][j] = a0;
    scomb[q][1][j] = a1;
    scomb[q][2][j] = a2;
    scomb[q][3][j] = a3;
    __syncthreads();

    // ---- fold by 256 epilogue threads; block-level stats ----
    const int ecc = t >> 6;        // 0..3 for t<256
    const int ej  = t & 63;
    float4 v = make_float4(0.f, 0.f, 0.f, 0.f);
    float ga_raw = 0.f, be = 0.f;

    if (t < 256) {
        #pragma unroll
        for (int r = 0; r < KSPLIT; r++) {
            const float4 p = scomb[r][ecc][ej];
            v.x += p.x; v.y += p.y; v.z += p.z; v.w += p.w;
        }
        const int c  = g * CPG + ecc;
        const float bb = bv[c];
        v.x += bb; v.y += bb; v.z += bb; v.w += bb;

        ga_raw = gamma[c];         // prefetch; hides under barrier
        be     = beta[c];

        float s  = v.x + v.y + v.z + v.w;
        float ss = v.x * v.x + v.y * v.y + v.z * v.z + v.w * v.w;
        #pragma unroll
        for (int o = 16; o > 0; o >>= 1) {
            s  += __shfl_xor_sync(0xffffffffu, s,  o);
            ss += __shfl_xor_sync(0xffffffffu, ss, o);
        }
        const int warp = t >> 5, lane = t & 31;     // warps 0..7
        if (lane == 0) { red_s[warp] = s; red_ss[warp] = ss; }
    }
    __syncthreads();

    // ---- t0 PUSHES its block partial into BOTH blocks' slots[half] ----
    if (t == 0) {
        float ts = 0.f, tss = 0.f;
        #pragma unroll
        for (int i = 0; i < 8; i++) { ts += red_s[i]; tss += red_ss[i]; }

        const uint32_t lslot = smem_u32(&slots[half]);
        uint32_t rslot;
        asm("mapa.shared::cluster.u32 %0, %1, %2;"
            : "=r"(rslot) : "r"(lslot), "r"(peer));
        asm volatile("st.shared::cluster.v2.f32 [%0], {%1, %2};"
                     :: "r"(rslot), "f"(ts), "f"(tss) : "memory");
        slots[half] = make_float2(ts, tss);
    }

    // ---- SINGLE cluster barrier: arrive(release) orders t0's remote store;
    //      wait(acquire) makes both slots visible to every thread ----
    asm volatile("barrier.cluster.arrive.aligned;" ::: "memory");
    asm volatile("barrier.cluster.wait.aligned;"   ::: "memory");

    // ---- redundant per-thread stats (fixed order -> deterministic),
    //      then normalize + affine + relu + store ----
    if (t < 256) {
        const float2 p0 = slots[0];
        const float2 p1 = slots[1];
        const float inv = 1.0f / (float)(CPG * N_DIM);
        const float m   = (p0.x + p1.x) * inv;
        const float var = (p0.y + p1.y) * inv - m * m;
        const float ga  = ga_raw * rsqrtf(var + EPS);

        const int c  = g * CPG + ecc;
        const int n0 = half * HALF_N + 4 * ej;

        float4 o4;
        o4.x = fmaxf(fmaf(v.x - m, ga, be), 0.f);
        o4.y = fmaxf(fmaf(v.y - m, ga, be), 0.f);
        o4.z = fmaxf(fmaf(v.z - m, ga, be), 0.f);
        o4.w = fmaxf(fmaf(v.w - m, ga, be), 0.f);
        *reinterpret_cast<float4*>(out + ((size_t)b * C_DIM + c) * N_DIM + n0) = o4;
    }
    // Exit safe: all remote stores happened before the cluster barrier; after
    // it, no thread touches peer SMEM.
}

extern "C" void kernel_launch(void* const* d_in, const int* in_sizes, int n_in,
                              void* d_out, int out_size)
{
    // 0 feat, 1 Wk, 2 bk, 3 Wq, 4 bq, 5 Wv, 6 bv, 7 gn_v_g, 8 gn_v_b, ...
    const float* feat = (const float*)d_in[0];
    const float* Wv   = (const float*)d_in[5];
    const float* bv   = (const float*)d_in[6];
    const float* gn_g = (const float*)d_in[7];
    const float* gn_b = (const float*)d_in[8];
    float* out = (float*)d_out;

    fused_onewave<<<B_DIM * GROUPS * HALVES, THREADS>>>(feat, Wv, bv, gn_g, gn_b, out);
}